// round 5
// baseline (speedup 1.0000x reference)
#include <cuda_runtime.h>

// out = relu(x @ (gamma*W3 + W4)^T)
// (reference softmax is over a size-1 axis == 1.0 -> attention is identity on
//  the W3 branch; W1/W2 are dead inputs)
//
// Persistent single-wave kernel: 148 blocks x 512 threads (1 block/SM).
// Grid-strided 64-row tiles, double-buffered smem staging (stage t+148 while
// computing t). Compute thread (cp, rl): owns 4 contiguous output columns
// [4cp, 4cp+4) -> one STG.128 per row; processes rows rl, rl+8, ... of the
// tile. Weights (4 rows of gamma*W3+W4) live in registers as packed f32x2;
// FFMA2 (fma.rn.f32x2) doubles the fp32 FMA rate. This halves LSU dispatch
// cost vs the 2-col version (STG.128 instead of 2x STG.64, half the LDS).

#define DICT 20
#define OUTC 200
#define NBLK 148
#define TPB 512
#define TILE 64
#define CPT 50                       // column-quad threads per row
#define RLANES 8                     // row lanes
#define RPT (TILE / RLANES)          // 8 rows per thread per tile
#define NCOMPUTE (CPT * RLANES)      // 400
#define STAGERS (TILE * DICT / 4)    // 320 float4 loads per tile

// ---- packed f32x2 helpers (sm_103a FFMA2 path, PTX-only) ----
__device__ __forceinline__ unsigned long long pack2(float lo, float hi) {
    unsigned long long r;
    asm("mov.b64 %0, {%1, %2};" : "=l"(r) : "f"(lo), "f"(hi));
    return r;
}
__device__ __forceinline__ unsigned long long fma2(unsigned long long a,
                                                   unsigned long long b,
                                                   unsigned long long c) {
    unsigned long long d;
    asm("fma.rn.f32x2 %0, %1, %2, %3;" : "=l"(d) : "l"(a), "l"(b), "l"(c));
    return d;
}
__device__ __forceinline__ unsigned long long mul2(unsigned long long a,
                                                   unsigned long long b) {
    unsigned long long d;
    asm("mul.rn.f32x2 %0, %1, %2;" : "=l"(d) : "l"(a), "l"(b));
    return d;
}
__device__ __forceinline__ float hadd_relu(unsigned long long v) {
    float2 f;
    asm("mov.b64 {%0, %1}, %2;" : "=f"(f.x), "=f"(f.y) : "l"(v));
    return fmaxf(f.x + f.y, 0.0f);
}

__global__ __launch_bounds__(TPB, 1)
void fused_gemm_relu(const float* __restrict__ x,
                     const float* __restrict__ W3,
                     const float* __restrict__ W4,
                     const float* __restrict__ gamma,
                     float* __restrict__ out, int ntiles) {
    __shared__ __align__(16) float xs[2][TILE * DICT];   // 2 x 5 KB

    const int tid = threadIdx.x;
    const int cp = tid % CPT;                 // cols [4cp, 4cp+4)
    const int rl = tid / CPT;                 // row lane 0..7
    const bool is_compute = (tid < NCOMPUTE);
    const bool is_stager  = (tid < STAGERS);

    // Build this thread's 4 combined weight rows in registers (packed f32x2).
    unsigned long long w0[10], w1[10], w2[10], w3[10];
    if (is_compute) {
        const float g = gamma[0];
        #pragma unroll
        for (int c = 0; c < 4; c++) {
            unsigned long long* wc = (c == 0) ? w0 : (c == 1) ? w1
                                   : (c == 2) ? w2 : w3;
            const float4* p3 = reinterpret_cast<const float4*>(W3 + (4 * cp + c) * DICT);
            const float4* p4 = reinterpret_cast<const float4*>(W4 + (4 * cp + c) * DICT);
            #pragma unroll
            for (int i = 0; i < 5; i++) {
                float4 a = p3[i], b = p4[i];
                wc[2 * i]     = pack2(fmaf(g, a.x, b.x), fmaf(g, a.y, b.y));
                wc[2 * i + 1] = pack2(fmaf(g, a.z, b.z), fmaf(g, a.w, b.w));
            }
        }
    }

    // Prologue: stage this block's first tile.
    if (blockIdx.x < ntiles && is_stager)
        *reinterpret_cast<float4*>(&xs[0][tid * 4]) =
            reinterpret_cast<const float4*>(x + (size_t)blockIdx.x * TILE * DICT)[tid];
    __syncthreads();

    int buf = 0;
    for (int t = blockIdx.x; t < ntiles; t += NBLK, buf ^= 1) {
        // Stage the next tile into the other buffer (overlaps compute below).
        const int tn = t + NBLK;
        if (tn < ntiles && is_stager)
            *reinterpret_cast<float4*>(&xs[buf ^ 1][tid * 4]) =
                reinterpret_cast<const float4*>(x + (size_t)tn * TILE * DICT)[tid];

        if (is_compute) {
            const float* xb = xs[buf];
            float4* o = reinterpret_cast<float4*>(
                            out + (size_t)(t * TILE + rl) * OUTC) + cp;
            #pragma unroll
            for (int i = 0; i < RPT; i++) {
                const ulonglong2* xp = reinterpret_cast<const ulonglong2*>(
                    xb + (rl + i * RLANES) * DICT);
                ulonglong2 v0 = xp[0], v1 = xp[1], v2 = xp[2],
                           v3 = xp[3], v4 = xp[4];

                unsigned long long a0, a1, a2, a3;
                a0 = mul2(v0.x, w0[0]);      a1 = mul2(v0.x, w1[0]);
                a2 = mul2(v0.x, w2[0]);      a3 = mul2(v0.x, w3[0]);
                a0 = fma2(v0.y, w0[1], a0);  a1 = fma2(v0.y, w1[1], a1);
                a2 = fma2(v0.y, w2[1], a2);  a3 = fma2(v0.y, w3[1], a3);
                a0 = fma2(v1.x, w0[2], a0);  a1 = fma2(v1.x, w1[2], a1);
                a2 = fma2(v1.x, w2[2], a2);  a3 = fma2(v1.x, w3[2], a3);
                a0 = fma2(v1.y, w0[3], a0);  a1 = fma2(v1.y, w1[3], a1);
                a2 = fma2(v1.y, w2[3], a2);  a3 = fma2(v1.y, w3[3], a3);
                a0 = fma2(v2.x, w0[4], a0);  a1 = fma2(v2.x, w1[4], a1);
                a2 = fma2(v2.x, w2[4], a2);  a3 = fma2(v2.x, w3[4], a3);
                a0 = fma2(v2.y, w0[5], a0);  a1 = fma2(v2.y, w1[5], a1);
                a2 = fma2(v2.y, w2[5], a2);  a3 = fma2(v2.y, w3[5], a3);
                a0 = fma2(v3.x, w0[6], a0);  a1 = fma2(v3.x, w1[6], a1);
                a2 = fma2(v3.x, w2[6], a2);  a3 = fma2(v3.x, w3[6], a3);
                a0 = fma2(v3.y, w0[7], a0);  a1 = fma2(v3.y, w1[7], a1);
                a2 = fma2(v3.y, w2[7], a2);  a3 = fma2(v3.y, w3[7], a3);
                a0 = fma2(v4.x, w0[8], a0);  a1 = fma2(v4.x, w1[8], a1);
                a2 = fma2(v4.x, w2[8], a2);  a3 = fma2(v4.x, w3[8], a3);
                a0 = fma2(v4.y, w0[9], a0);  a1 = fma2(v4.y, w1[9], a1);
                a2 = fma2(v4.y, w2[9], a2);  a3 = fma2(v4.y, w3[9], a3);

                *o = make_float4(hadd_relu(a0), hadd_relu(a1),
                                 hadd_relu(a2), hadd_relu(a3));  // STG.128
                o += (RLANES * OUTC) / 4;    // 8 rows ahead
            }
        }
        __syncthreads();   // compute(t) done AND stage(next) done
    }
}

extern "C" void kernel_launch(void* const* d_in, const int* in_sizes, int n_in,
                              void* d_out, int out_size) {
    const float* x     = (const float*)d_in[0];
    // d_in[1] = W1, d_in[2] = W2 : dead (softmax over size-1 axis == 1)
    const float* W3    = (const float*)d_in[3];
    const float* W4    = (const float*)d_in[4];
    const float* gamma = (const float*)d_in[5];
    float* out = (float*)d_out;

    const int B = in_sizes[0] / DICT;   // 262144
    const int ntiles = B / TILE;        // 4096 (exact)

    fused_gemm_relu<<<NBLK, TPB>>>(x, W3, W4, gamma, out, ntiles);
}